// round 16
// baseline (speedup 1.0000x reference)
#include <cuda_runtime.h>
#include <cuda_fp16.h>
#include <cstdint>

#define DEVINL __device__ __forceinline__

// ---------------- problem constants ----------------
static constexpr int BATCH = 4;
static constexpr int NSEQ  = 4096;
static constexpr int DDIM  = 512;
// scale * log2(e): logits kept in log2 domain so epilogue is a bare ex2.approx
static constexpr float CLOG2E = 0.09016844005556021f;

// ---------------- tiling ----------------
static constexpr int MT    = 128;            // q rows per unit
static constexpr int NTILE = 128;            // kv rows per unit
static constexpr int KC    = 64;             // k per chunk (128B smem rows)
static constexpr int QTILES = BATCH * NSEQ / MT;   // 128
static constexpr int NTC    = NSEQ / NTILE;        // 32
static constexpr int UNITS  = QTILES * NTC;        // 4096 work units
static constexpr int STAGES = 2;                   // double buffer
static constexpr int THREADS = 256;                // 8 warps: 2 M x 4 N (64x32 tiles)

static constexpr int AB  = MT * KC * 2;          // 16384
static constexpr int BB  = NTILE * KC * 2;       // 16384
static constexpr int STB = AB + BB;              // 32768 per stage
static constexpr int SMEM_TOTAL = 1024 + STAGES * STB;   // 66560 -> 3 CTAs/SM

// ---------------- scratch (device globals: no allocs allowed) ----------------
__device__ __align__(1024) __half g_q16[(size_t)BATCH * NSEQ * DDIM];  // q * CLOG2E
__device__ __align__(1024) __half g_k16[(size_t)BATCH * NSEQ * DDIM];  // k
__device__ float g_diagexp[BATCH * NSEQ];
__device__ float g_rsum[BATCH * NSEQ];
__device__ int   g_unit;                          // work-stealing unit counter

// ---------------- PTX helpers ----------------
DEVINL uint32_t smem_u32(const void* p) {
    uint32_t a;
    asm("{ .reg .u64 t; cvta.to.shared.u64 t, %1; cvt.u32.u64 %0, t; }"
        : "=r"(a) : "l"(p));
    return a;
}
DEVINL uint32_t sw128(uint32_t off) { return off ^ ((off >> 3) & 0x70); }

DEVINL void cp_async16(uint32_t dst, const void* src) {
    asm volatile("cp.async.cg.shared.global [%0], [%1], 16;"
                 :: "r"(dst), "l"(src) : "memory");
}
DEVINL void cp_commit() { asm volatile("cp.async.commit_group;" ::: "memory"); }
template <int N>
DEVINL void cp_wait_group() { asm volatile("cp.async.wait_group %0;" :: "n"(N) : "memory"); }

DEVINL void ldsm4(uint32_t (&r)[4], uint32_t addr) {
    asm volatile("ldmatrix.sync.aligned.m8n8.x4.shared.b16 {%0,%1,%2,%3}, [%4];"
                 : "=r"(r[0]), "=r"(r[1]), "=r"(r[2]), "=r"(r[3]) : "r"(addr));
}
// fp16-accumulate MMA: D (2 regs = 4 halves) += A*B
DEVINL void mma_f16acc(uint32_t* d, const uint32_t* a, uint32_t b0, uint32_t b1) {
    asm volatile(
        "mma.sync.aligned.m16n8k16.row.col.f16.f16.f16.f16 "
        "{%0,%1}, {%2,%3,%4,%5}, {%6,%7}, {%0,%1};"
        : "+r"(d[0]), "+r"(d[1])
        : "r"(a[0]), "r"(a[1]), "r"(a[2]), "r"(a[3]), "r"(b0), "r"(b1));
}
DEVINL float ex2(float x) {
    float y;
    asm("ex2.approx.ftz.f32 %0, %1;" : "=f"(y) : "f"(x));
    return y;
}

// ---------------- prep: convert to fp16 + fused exact fp32 diagonal ----------------
// 512 threads = 4 rows/block (128 threads per 512-elem row, 4 warps/row)
__global__ void __launch_bounds__(512) prep_kernel(const float* __restrict__ q,
                                                   const float* __restrict__ kv) {
    __shared__ float part[16];   // 4 rows x 4 warps

    size_t idx = (size_t)blockIdx.x * 512 + threadIdx.x;  // float4 id (exact grid)
    size_t o   = idx << 2;

    float4 a = reinterpret_cast<const float4*>(q)[idx];
    float4 b = reinterpret_cast<const float4*>(kv)[idx];

    {
        __half2* p = reinterpret_cast<__half2*>(g_q16 + o);
        p[0] = __halves2half2(__float2half(a.x * CLOG2E), __float2half(a.y * CLOG2E));
        p[1] = __halves2half2(__float2half(a.z * CLOG2E), __float2half(a.w * CLOG2E));
    }
    {
        __half2* p = reinterpret_cast<__half2*>(g_k16 + o);
        p[0] = __halves2half2(__float2half(b.x), __float2half(b.y));
        p[1] = __halves2half2(__float2half(b.z), __float2half(b.w));
    }

    // fused diagonal: partial dot of this thread's 4 elements (exact fp32 inputs)
    float s = a.x * b.x + a.y * b.y + a.z * b.z + a.w * b.w;
#pragma unroll
    for (int off = 16; off; off >>= 1) s += __shfl_xor_sync(0xffffffffu, s, off);
    const int w = threadIdx.x >> 5;
    if ((threadIdx.x & 31) == 0) part[w] = s;
    __syncthreads();
    if (threadIdx.x < 4) {
        const int row = blockIdx.x * 4 + threadIdx.x;
        float d = part[threadIdx.x * 4] + part[threadIdx.x * 4 + 1]
                + part[threadIdx.x * 4 + 2] + part[threadIdx.x * 4 + 3];
        g_diagexp[row] = exp2f(CLOG2E * d);
        g_rsum[row] = 0.f;
    }
    if (blockIdx.x == 0 && threadIdx.x == 0) g_unit = 0;
}

// ---------------- main GEMM + normalizer: persistent, 3 CTAs/SM ----------------
__global__ void __launch_bounds__(THREADS, 3) main_kernel() {
    extern __shared__ char smem_raw[];
    __shared__ int s_u;
    const uint32_t st0 = (smem_u32(smem_raw) + 1023u) & ~1023u;

    const int tid  = threadIdx.x;
    const int wid  = tid >> 5;
    const int lane = tid & 31;

    // cp.async descriptors are affine in the vector index i:
    //   j = tid & 7 invariant, r = (tid>>3) + 32*i  ->  smem dst += 4096,
    //   gmem off += 32*DDIM per i (swizzle unaffected: r%8 invariant).
    const int r0 = tid >> 3, j0 = tid & 7;
    const uint32_t sd0 = sw128((uint32_t)(r0 * 128 + j0 * 16));
    const int      go0 = r0 * DDIM + j0 * 8;

    // load chunk cc of unit u into the given stage (A 128x64 + B 128x64)
    auto issue = [&](int u, int cc, int stage) {
        const int qt = u & (QTILES - 1), nt = u >> 7;
        const uint32_t sA = st0 + stage * STB;
        const uint32_t sB = sA + AB;
        const __half* qs = g_q16 + (size_t)qt * MT * DDIM + cc * KC + go0;
#pragma unroll
        for (int i = 0; i < 4; ++i)
            cp_async16(sA + sd0 + i * 4096, qs + i * 32 * DDIM);
        const __half* ks = g_k16 +
            ((size_t)(qt >> 5) * NSEQ + (size_t)nt * NTILE) * DDIM + cc * KC + go0;
#pragma unroll
        for (int i = 0; i < 4; ++i)
            cp_async16(sB + sd0 + i * 4096, ks + i * 32 * DDIM);
        cp_commit();
    };

    // warp tile: 2 M-warps x 4 N-warps, each 64x32
    const int m0 = (wid & 1) * 64;
    const int n0 = (wid >> 1) * 32;
    const int lr  = lane & 15;          // ldmatrix row within 16
    const int lcb = (lane >> 4) * 16;   // ldmatrix 16B column group

    uint32_t aBase[4], aSw[4], bBase[2], bSw[2];
#pragma unroll
    for (int f = 0; f < 4; ++f) {
        int ra = m0 + f * 16 + lr;
        aBase[f] = (uint32_t)(ra * 128); aSw[f] = (uint32_t)((ra & 7) << 4);
    }
#pragma unroll
    for (int f = 0; f < 2; ++f) {
        int rb = n0 + f * 16 + lr;
        bBase[f] = (uint32_t)(rb * 128); bSw[f] = (uint32_t)((rb & 7) << 4);
    }

    // fp16 accumulators: 4 M-frags x 4 N-frags
    uint32_t ch[4][4][2];
#pragma unroll
    for (int mf = 0; mf < 4; ++mf)
#pragma unroll
        for (int nf = 0; nf < 4; ++nf) { ch[mf][nf][0] = 0u; ch[mf][nf][1] = 0u; }

    // initial unit grab (grid <= UNITS, so first grab always valid)
    if (tid == 0) s_u = atomicAdd(&g_unit, 1);
    __syncthreads();
    int u_cur = s_u;

    int par = 0;
    issue(u_cur, 0, 0);

    for (;;) {
        int u_nxt = UNITS;
#pragma unroll 1
        for (int cc = 0; cc < 8; ++cc) {
            cp_wait_group<0>();        // current stage ready
            __syncthreads();           // all warps done with the other stage
            if (cc < 7) {
                issue(u_cur, cc + 1, par ^ 1);
            } else {
                if (tid == 0) s_u = atomicAdd(&g_unit, 1);
                __syncthreads();
                u_nxt = s_u;
                if (u_nxt < UNITS) issue(u_nxt, 0, par ^ 1);
            }

            const uint32_t sA = st0 + par * STB;
            const uint32_t sB = sA + AB;

#pragma unroll
            for (int kk = 0; kk < 4; ++kk) {
                const uint32_t cb = (uint32_t)(kk * 32) + lcb;
                uint32_t a[4][4], b[2][4];
#pragma unroll
                for (int f = 0; f < 2; ++f) ldsm4(b[f], sB + bBase[f] + (cb ^ bSw[f]));
#pragma unroll
                for (int f = 0; f < 4; ++f) ldsm4(a[f], sA + aBase[f] + (cb ^ aSw[f]));
#pragma unroll
                for (int mf = 0; mf < 4; ++mf)
#pragma unroll
                    for (int g = 0; g < 2; ++g) {
                        mma_f16acc(ch[mf][2 * g],     a[mf], b[g][0], b[g][2]);
                        mma_f16acc(ch[mf][2 * g + 1], a[mf], b[g][1], b[g][3]);
                    }
            }

            if (cc == 7) {
                // unit epilogue: rowsum of 2^score (fp32 ex2) -> global accumulators
                const int qt = u_cur & (QTILES - 1);
                float* rs = g_rsum + qt * MT;
#pragma unroll
                for (int mf = 0; mf < 4; ++mf) {
                    float s0 = 0.f, s1 = 0.f;
#pragma unroll
                    for (int nf = 0; nf < 4; ++nf) {
                        float2 h0 = __half22float2(*reinterpret_cast<__half2*>(&ch[mf][nf][0]));
                        float2 h1 = __half22float2(*reinterpret_cast<__half2*>(&ch[mf][nf][1]));
                        s0 += ex2(h0.x) + ex2(h0.y);
                        s1 += ex2(h1.x) + ex2(h1.y);
                        ch[mf][nf][0] = 0u; ch[mf][nf][1] = 0u;
                    }
                    s0 += __shfl_xor_sync(0xffffffffu, s0, 1);
                    s0 += __shfl_xor_sync(0xffffffffu, s0, 2);
                    s1 += __shfl_xor_sync(0xffffffffu, s1, 1);
                    s1 += __shfl_xor_sync(0xffffffffu, s1, 2);
                    if ((lane & 3) == 0) {
                        atomicAdd(&rs[m0 + mf * 16 + (lane >> 2)], s0);
                        atomicAdd(&rs[m0 + mf * 16 + 8 + (lane >> 2)], s1);
                    }
                }
            }
            par ^= 1;
        }
        u_cur = u_nxt;
        if (u_cur >= UNITS) break;
    }
}

// ---------------- final: out = diagexp / rowsum ----------------
__global__ void __launch_bounds__(256) out_kernel(float* __restrict__ out) {
    int row = blockIdx.x * 256 + threadIdx.x;
    out[row] = g_diagexp[row] / g_rsum[row];
}

extern "C" void kernel_launch(void* const* d_in, const int* in_sizes, int n_in,
                              void* d_out, int out_size) {
    const float* q  = (const float*)d_in[0];
    const float* kv = (const float*)d_in[1];
    float* out = (float*)d_out;

    int nsm = 0;
    cudaDeviceGetAttribute(&nsm, cudaDevAttrMultiProcessorCount, 0);
    if (nsm <= 0) nsm = 148;
    int grid = 3 * nsm;                 // 3 CTAs per SM
    if (grid > UNITS) grid = UNITS;

    prep_kernel<<<4096, 512>>>(q, kv);

    cudaFuncSetAttribute(main_kernel, cudaFuncAttributeMaxDynamicSharedMemorySize,
                         SMEM_TOTAL);
    main_kernel<<<grid, THREADS, SMEM_TOTAL>>>();

    out_kernel<<<BATCH * NSEQ / 256, 256>>>(out);
}

// round 17
// speedup vs baseline: 1.0133x; 1.0133x over previous
#include <cuda_runtime.h>
#include <cuda_fp16.h>
#include <cstdint>

#define DEVINL __device__ __forceinline__

// ---------------- problem constants ----------------
static constexpr int BATCH = 4;
static constexpr int NSEQ  = 4096;
static constexpr int DDIM  = 512;
// scale * log2(e): logits kept in log2 domain so epilogue is a bare ex2.approx
static constexpr float CLOG2E = 0.09016844005556021f;

// ---------------- tiling ----------------
static constexpr int MT    = 128;            // q rows per unit
static constexpr int NTILE = 256;            // kv rows per unit
static constexpr int KC    = 64;             // k per chunk (128B smem rows)
static constexpr int QTILES = BATCH * NSEQ / MT;   // 128
static constexpr int NTC    = NSEQ / NTILE;        // 16
static constexpr int UNITS  = QTILES * NTC;        // 2048 work units
static constexpr int STAGES = 2;                   // double buffer (2 CTAs/SM)
static constexpr int THREADS = 256;                // 8 warps: 2 M x 4 N

static constexpr int AB  = MT * KC * 2;          // 16384
static constexpr int BB  = NTILE * KC * 2;       // 32768
static constexpr int STB = AB + BB;              // 49152 per stage
static constexpr int SMEM_TOTAL = 1024 + STAGES * STB;   // 99328 -> 2 CTAs/SM

// ---------------- scratch (device globals: no allocs allowed) ----------------
__device__ __align__(1024) __half g_q16[(size_t)BATCH * NSEQ * DDIM];  // q * CLOG2E
__device__ __align__(1024) __half g_k16[(size_t)BATCH * NSEQ * DDIM];  // k
__device__ float g_diagexp[BATCH * NSEQ];
__device__ float g_rsum[BATCH * NSEQ];
__device__ int   g_unit;                          // work-stealing unit counter

// ---------------- PTX helpers ----------------
DEVINL uint32_t smem_u32(const void* p) {
    uint32_t a;
    asm("{ .reg .u64 t; cvta.to.shared.u64 t, %1; cvt.u32.u64 %0, t; }"
        : "=r"(a) : "l"(p));
    return a;
}
DEVINL uint32_t sw128(uint32_t off) { return off ^ ((off >> 3) & 0x70); }

DEVINL void cp_async16(uint32_t dst, const void* src) {
    asm volatile("cp.async.cg.shared.global [%0], [%1], 16;"
                 :: "r"(dst), "l"(src) : "memory");
}
DEVINL void cp_commit() { asm volatile("cp.async.commit_group;" ::: "memory"); }
template <int N>
DEVINL void cp_wait_group() { asm volatile("cp.async.wait_group %0;" :: "n"(N) : "memory"); }

DEVINL void ldsm4(uint32_t (&r)[4], uint32_t addr) {
    asm volatile("ldmatrix.sync.aligned.m8n8.x4.shared.b16 {%0,%1,%2,%3}, [%4];"
                 : "=r"(r[0]), "=r"(r[1]), "=r"(r[2]), "=r"(r[3]) : "r"(addr));
}
// fp16-accumulate MMA: D (2 regs = 4 halves) += A*B
DEVINL void mma_f16acc(uint32_t* d, const uint32_t* a, uint32_t b0, uint32_t b1) {
    asm volatile(
        "mma.sync.aligned.m16n8k16.row.col.f16.f16.f16.f16 "
        "{%0,%1}, {%2,%3,%4,%5}, {%6,%7}, {%0,%1};"
        : "+r"(d[0]), "+r"(d[1])
        : "r"(a[0]), "r"(a[1]), "r"(a[2]), "r"(a[3]), "r"(b0), "r"(b1));
}
DEVINL float ex2(float x) {
    float y;
    asm("ex2.approx.ftz.f32 %0, %1;" : "=f"(y) : "f"(x));
    return y;
}

// ---------------- prep: convert to fp16 + fused exact fp32 diagonal ----------------
// 512 threads = 4 rows/block (128 threads per 512-elem row, 4 warps/row)
__global__ void __launch_bounds__(512) prep_kernel(const float* __restrict__ q,
                                                   const float* __restrict__ kv) {
    __shared__ float part[16];   // 4 rows x 4 warps

    size_t idx = (size_t)blockIdx.x * 512 + threadIdx.x;  // float4 id (exact grid)
    size_t o   = idx << 2;

    float4 a = reinterpret_cast<const float4*>(q)[idx];
    float4 b = reinterpret_cast<const float4*>(kv)[idx];

    {
        __half2* p = reinterpret_cast<__half2*>(g_q16 + o);
        p[0] = __halves2half2(__float2half(a.x * CLOG2E), __float2half(a.y * CLOG2E));
        p[1] = __halves2half2(__float2half(a.z * CLOG2E), __float2half(a.w * CLOG2E));
    }
    {
        __half2* p = reinterpret_cast<__half2*>(g_k16 + o);
        p[0] = __halves2half2(__float2half(b.x), __float2half(b.y));
        p[1] = __halves2half2(__float2half(b.z), __float2half(b.w));
    }

    // fused diagonal: partial dot of this thread's 4 elements (exact fp32 inputs)
    float s = a.x * b.x + a.y * b.y + a.z * b.z + a.w * b.w;
#pragma unroll
    for (int off = 16; off; off >>= 1) s += __shfl_xor_sync(0xffffffffu, s, off);
    const int w = threadIdx.x >> 5;
    if ((threadIdx.x & 31) == 0) part[w] = s;
    __syncthreads();
    if (threadIdx.x < 4) {
        const int row = blockIdx.x * 4 + threadIdx.x;
        float d = part[threadIdx.x * 4] + part[threadIdx.x * 4 + 1]
                + part[threadIdx.x * 4 + 2] + part[threadIdx.x * 4 + 3];
        g_diagexp[row] = exp2f(CLOG2E * d);
        g_rsum[row] = 0.f;
    }
    if (blockIdx.x == 0 && threadIdx.x == 0) g_unit = 0;
}

// ---------------- main GEMM + normalizer: persistent, work-stealing ----------------
__global__ void __launch_bounds__(THREADS, 2) main_kernel() {
    extern __shared__ char smem_raw[];
    __shared__ int s_u;
    const uint32_t st0 = (smem_u32(smem_raw) + 1023u) & ~1023u;

    const int tid  = threadIdx.x;
    const int wid  = tid >> 5;
    const int lane = tid & 31;

    // cp.async descriptors are affine in the vector index i:
    //   j = tid & 7 invariant, r = (tid>>3) + 32*i  ->  smem dst += 4096,
    //   gmem off += 32*DDIM per i (swizzle unaffected: r%8 invariant).
    const int r0 = tid >> 3, j0 = tid & 7;
    const uint32_t sd0 = sw128((uint32_t)(r0 * 128 + j0 * 16));
    const int      go0 = r0 * DDIM + j0 * 8;

    // load chunk cc of unit u into the given stage
    auto issue = [&](int u, int cc, int stage) {
        const int qt = u & (QTILES - 1), nt = u >> 7;
        const uint32_t sA = st0 + stage * STB;
        const uint32_t sB = sA + AB;
        const __half* qs = g_q16 + (size_t)qt * MT * DDIM + cc * KC + go0;
#pragma unroll
        for (int i = 0; i < 4; ++i)
            cp_async16(sA + sd0 + i * 4096, qs + i * 32 * DDIM);
        const __half* ks = g_k16 +
            ((size_t)(qt >> 5) * NSEQ + (size_t)nt * NTILE) * DDIM + cc * KC + go0;
#pragma unroll
        for (int i = 0; i < 8; ++i)
            cp_async16(sB + sd0 + i * 4096, ks + i * 32 * DDIM);
        cp_commit();
    };

    // warp tile: 2 M-warps x 4 N-warps, each 64x64
    const int m0 = (wid & 1) * 64;
    const int n0 = (wid >> 1) * 64;
    const int lr  = lane & 15;          // ldmatrix row within 16
    const int lcb = (lane >> 4) * 16;   // ldmatrix 16B column group

    uint32_t aBase[4], aSw[4], bBase[4], bSw[4];
#pragma unroll
    for (int f = 0; f < 4; ++f) {
        int ra = m0 + f * 16 + lr;
        aBase[f] = (uint32_t)(ra * 128); aSw[f] = (uint32_t)((ra & 7) << 4);
        int rb = n0 + f * 16 + lr;
        bBase[f] = (uint32_t)(rb * 128); bSw[f] = (uint32_t)((rb & 7) << 4);
    }

    // fp16 accumulators
    uint32_t ch[4][8][2];
#pragma unroll
    for (int mf = 0; mf < 4; ++mf)
#pragma unroll
        for (int nf = 0; nf < 8; ++nf) { ch[mf][nf][0] = 0u; ch[mf][nf][1] = 0u; }

    // initial unit grab (grid <= UNITS, so first grab always valid)
    if (tid == 0) s_u = atomicAdd(&g_unit, 1);
    __syncthreads();
    int u_cur = s_u;

    int par = 0;
    issue(u_cur, 0, 0);

    for (;;) {
        int u_nxt = UNITS;
#pragma unroll 1
        for (int cc = 0; cc < 8; ++cc) {
            cp_wait_group<0>();        // current stage ready
            __syncthreads();           // all warps done with the other stage
            if (cc == 0) {
                // early grab: atomic latency hidden behind 7 chunks of compute;
                // the intervening per-chunk barriers order s_u for the cc==7 read
                if (tid == 0) s_u = atomicAdd(&g_unit, 1);
                issue(u_cur, 1, par ^ 1);
            } else if (cc < 7) {
                issue(u_cur, cc + 1, par ^ 1);
            } else {
                u_nxt = s_u;           // ordered by the cc==1..7 barriers
                if (u_nxt < UNITS) issue(u_nxt, 0, par ^ 1);
            }

            const uint32_t sA = st0 + par * STB;
            const uint32_t sB = sA + AB;

#pragma unroll
            for (int kk = 0; kk < 4; ++kk) {
                const uint32_t cb = (uint32_t)(kk * 32) + lcb;
                uint32_t a[4][4], b[4][4];
#pragma unroll
                for (int f = 0; f < 4; ++f) ldsm4(b[f], sB + bBase[f] + (cb ^ bSw[f]));
#pragma unroll
                for (int f = 0; f < 4; ++f) ldsm4(a[f], sA + aBase[f] + (cb ^ aSw[f]));
#pragma unroll
                for (int mf = 0; mf < 4; ++mf)
#pragma unroll
                    for (int g = 0; g < 4; ++g) {
                        mma_f16acc(ch[mf][2 * g],     a[mf], b[g][0], b[g][2]);
                        mma_f16acc(ch[mf][2 * g + 1], a[mf], b[g][1], b[g][3]);
                    }
            }

            if (cc == 7) {
                // unit epilogue: rowsum of 2^score (fp32 ex2) -> global accumulators
                const int qt = u_cur & (QTILES - 1);
                float* rs = g_rsum + qt * MT;
#pragma unroll
                for (int mf = 0; mf < 4; ++mf) {
                    float s0 = 0.f, s1 = 0.f;
#pragma unroll
                    for (int nf = 0; nf < 8; ++nf) {
                        float2 h0 = __half22float2(*reinterpret_cast<__half2*>(&ch[mf][nf][0]));
                        float2 h1 = __half22float2(*reinterpret_cast<__half2*>(&ch[mf][nf][1]));
                        s0 += ex2(h0.x) + ex2(h0.y);
                        s1 += ex2(h1.x) + ex2(h1.y);
                        ch[mf][nf][0] = 0u; ch[mf][nf][1] = 0u;
                    }
                    s0 += __shfl_xor_sync(0xffffffffu, s0, 1);
                    s0 += __shfl_xor_sync(0xffffffffu, s0, 2);
                    s1 += __shfl_xor_sync(0xffffffffu, s1, 1);
                    s1 += __shfl_xor_sync(0xffffffffu, s1, 2);
                    if ((lane & 3) == 0) {
                        atomicAdd(&rs[m0 + mf * 16 + (lane >> 2)], s0);
                        atomicAdd(&rs[m0 + mf * 16 + 8 + (lane >> 2)], s1);
                    }
                }
            }
            par ^= 1;
        }
        u_cur = u_nxt;
        if (u_cur >= UNITS) break;
    }
}

// ---------------- final: out = diagexp / rowsum ----------------
__global__ void __launch_bounds__(256) out_kernel(float* __restrict__ out) {
    int row = blockIdx.x * 256 + threadIdx.x;
    out[row] = g_diagexp[row] / g_rsum[row];
}

extern "C" void kernel_launch(void* const* d_in, const int* in_sizes, int n_in,
                              void* d_out, int out_size) {
    const float* q  = (const float*)d_in[0];
    const float* kv = (const float*)d_in[1];
    float* out = (float*)d_out;

    int nsm = 0;
    cudaDeviceGetAttribute(&nsm, cudaDevAttrMultiProcessorCount, 0);
    if (nsm <= 0) nsm = 148;
    int grid = 2 * nsm;                 // 2 CTAs per SM
    if (grid > UNITS) grid = UNITS;

    prep_kernel<<<4096, 512>>>(q, kv);

    cudaFuncSetAttribute(main_kernel, cudaFuncAttributeMaxDynamicSharedMemorySize,
                         SMEM_TOTAL);
    main_kernel<<<grid, THREADS, SMEM_TOTAL>>>();

    out_kernel<<<BATCH * NSEQ / 256, 256>>>(out);
}